// round 2
// baseline (speedup 1.0000x reference)
#include <cuda_runtime.h>

#define B_  4
#define N_  256
#define T_  64
#define D_  128
#define DH_ 128
#define DR_ 32
#define WLD (3*D_+DR_)   // 416

// ---------------- scratch (device globals; no allocations allowed) ----------
__device__ float g_q [B_*N_*T_*DH_];   // (b,i,t,h)
__device__ float g_k [B_*N_*T_*DH_];   // (b,j,t,h)
__device__ float g_qr[B_*N_*T_*DR_];   // (b,i,t,r)  = q @ Wr
__device__ float g_qb[B_*N_*T_];       // (b,i,t)    = q @ br
__device__ float g_s1[B_*T_*N_*N_];    // (b,t,i,j)  = q.k
__device__ float g_w [B_*N_*T_*N_];    // (b,i,t,j)  softmax weights (diag-masked)
__device__ float g_ws[B_*N_*T_];       // (b,i,t)    = sum_j w
__device__ float g_ds[B_*N_*D_];       // (b,j,d)    = sum_t delta_H
__device__ float g_Hw[B_*N_*T_*D_];    // (b,i,t,d)  = sum_j w * H[b,j,t,:]
__device__ float g_Dw[B_*N_*T_*D_];    // (b,i,t,d)  = sum_j w * dsum[b,j,:]
__device__ float g_Rw[B_*N_*T_*DR_];   // (b,i,t,r)  = sum_j w * R[b,i,j,:]

// ---------------- 64x128 tile, K-chunk 32, 256 threads, 4x8 per thread ------
__device__ __forceinline__ void mma_64x128(const float* __restrict__ As,
                                           const float* __restrict__ Bs,
                                           float acc[4][8], int ty, int tx) {
#pragma unroll
  for (int kk = 0; kk < 32; kk++) {
    float a[4], bv[8];
#pragma unroll
    for (int ii = 0; ii < 4; ii++) a[ii] = As[(ty*4+ii)*33 + kk];
#pragma unroll
    for (int jj = 0; jj < 8; jj++) bv[jj] = Bs[kk*129 + tx*8 + jj];
#pragma unroll
    for (int ii = 0; ii < 4; ii++)
#pragma unroll
      for (int jj = 0; jj < 8; jj++) acc[ii][jj] = fmaf(a[ii], bv[jj], acc[ii][jj]);
  }
}

// ---------------- K1: q = H Wq^T + bq, k = H Wk^T + bk (per (b,i)) ----------
__global__ __launch_bounds__(256)
void k_proj(const float* __restrict__ H,
            const float* __restrict__ Wq, const float* __restrict__ bq,
            const float* __restrict__ Wk, const float* __restrict__ bk) {
  extern __shared__ float sm[];
  float* As = sm;             // 64*33
  float* Bq = As + 64*33;     // 32*129
  float* Bk = Bq + 32*129;    // 32*129
  int bi = blockIdx.x;
  int tid = threadIdx.x, ty = tid >> 4, tx = tid & 15;
  const float* Hrow = H + (size_t)bi*T_*D_;

  float aq[4][8], ak[4][8];
#pragma unroll
  for (int ii=0;ii<4;ii++)
#pragma unroll
    for (int jj=0;jj<8;jj++){ aq[ii][jj]=0.f; ak[ii][jj]=0.f; }

  for (int kc = 0; kc < 4; kc++) {
    int c0 = kc*32;
    // 64 rows x 32 cols, float4: 64*8 = 512 vec loads
    for (int l = tid; l < 64*8; l += 256) {
      int r = l >> 3, c4 = l & 7;
      float4 v = *(const float4*)(Hrow + r*D_ + c0 + c4*4);
      As[r*33+c4*4+0] = v.x; As[r*33+c4*4+1] = v.y;
      As[r*33+c4*4+2] = v.z; As[r*33+c4*4+3] = v.w;
    }
    for (int l = tid; l < 128*8; l += 256) {
      int e = l >> 3, c4 = l & 7;
      float4 vq = *(const float4*)(Wq + e*D_ + c0 + c4*4);
      float4 vk = *(const float4*)(Wk + e*D_ + c0 + c4*4);
      Bq[(c4*4+0)*129+e] = vq.x; Bq[(c4*4+1)*129+e] = vq.y;
      Bq[(c4*4+2)*129+e] = vq.z; Bq[(c4*4+3)*129+e] = vq.w;
      Bk[(c4*4+0)*129+e] = vk.x; Bk[(c4*4+1)*129+e] = vk.y;
      Bk[(c4*4+2)*129+e] = vk.z; Bk[(c4*4+3)*129+e] = vk.w;
    }
    __syncthreads();
    mma_64x128(As, Bq, aq, ty, tx);
    mma_64x128(As, Bk, ak, ty, tx);
    __syncthreads();
  }
  float* qout = g_q + (size_t)bi*T_*DH_;
  float* kout = g_k + (size_t)bi*T_*DH_;
#pragma unroll
  for (int ii=0;ii<4;ii++){
    int t = ty*4+ii;
#pragma unroll
    for (int jj=0;jj<8;jj++){
      int h = tx*8+jj;
      qout[t*DH_+h] = aq[ii][jj] + bq[h];
      kout[t*DH_+h] = ak[ii][jj] + bk[h];
    }
  }
}

// ---------------- K1b: qr = q Wr, qb = q . br (per (b,i)) -------------------
__global__ __launch_bounds__(256)
void k_qr(const float* __restrict__ Wr, const float* __restrict__ br) {
  extern __shared__ float sm[];   // Qs[64][130]
  float* Qs = sm;
  int bi = blockIdx.x, tid = threadIdx.x;
  const float* qsrc = g_q + (size_t)bi*T_*DH_;
  for (int l = tid; l < T_*DH_/4; l += 256) {
    int t = l >> 5, c4 = l & 31;
    float4 v = *(const float4*)(qsrc + t*DH_ + c4*4);
    Qs[t*130+c4*4+0] = v.x; Qs[t*130+c4*4+1] = v.y;
    Qs[t*130+c4*4+2] = v.z; Qs[t*130+c4*4+3] = v.w;
  }
  __syncthreads();
  int t = tid >> 2, rg = tid & 3;
  float acc[8];
#pragma unroll
  for (int rr=0;rr<8;rr++) acc[rr]=0.f;
  for (int h = 0; h < DH_; h++) {
    float qv = Qs[t*130+h];
#pragma unroll
    for (int rr=0;rr<8;rr++) acc[rr] = fmaf(qv, Wr[h*DR_ + rg*8 + rr], acc[rr]);
  }
  float* qrout = g_qr + (size_t)bi*T_*DR_ + t*DR_ + rg*8;
#pragma unroll
  for (int rr=0;rr<8;rr++) qrout[rr] = acc[rr];

  if (tid < T_) {
    float s = 0.f;
    for (int h = 0; h < DH_; h++) s = fmaf(Qs[tid*130+h], br[h], s);
    g_qb[(size_t)bi*T_ + tid] = s;
  }
}

// ---------------- K2: dsum = sum_t delta_H --------------------------------
__global__ __launch_bounds__(128)
void k_dsum(const float* __restrict__ dH) {
  int bj = blockIdx.x, d = threadIdx.x;
  const float* p = dH + (size_t)bj*T_*D_ + d;
  float s = 0.f;
#pragma unroll 8
  for (int t = 0; t < T_; t++) s += p[t*D_];
  g_ds[(size_t)bj*D_ + d] = s;
}

// ---------------- K3: s1[b,t,i,j] = q.k   (per (b,t), tiled) ----------------
__global__ __launch_bounds__(256)
void k_s1() {
  extern __shared__ float sm[];
  float* As = sm;            // 64*33
  float* Bs = As + 64*33;    // 32*129
  int bt = blockIdx.y;
  int b = bt / T_, t = bt % T_;
  int i0 = (blockIdx.x & 3) * 64;
  int j0 = (blockIdx.x >> 2) * 128;
  int tid = threadIdx.x, ty = tid >> 4, tx = tid & 15;
  float acc[4][8];
#pragma unroll
  for (int ii=0;ii<4;ii++)
#pragma unroll
    for (int jj=0;jj<8;jj++) acc[ii][jj]=0.f;

  for (int kc = 0; kc < 4; kc++) {
    int h0 = kc*32;
    for (int l = tid; l < 64*8; l += 256) {
      int r = l >> 3, c4 = l & 7;
      float4 v = *(const float4*)(g_q + (((size_t)b*N_ + i0+r)*T_ + t)*DH_ + h0 + c4*4);
      As[r*33+c4*4+0] = v.x; As[r*33+c4*4+1] = v.y;
      As[r*33+c4*4+2] = v.z; As[r*33+c4*4+3] = v.w;
    }
    for (int l = tid; l < 128*8; l += 256) {
      int jj = l >> 3, c4 = l & 7;
      float4 v = *(const float4*)(g_k + (((size_t)b*N_ + j0+jj)*T_ + t)*DH_ + h0 + c4*4);
      Bs[(c4*4+0)*129+jj] = v.x; Bs[(c4*4+1)*129+jj] = v.y;
      Bs[(c4*4+2)*129+jj] = v.z; Bs[(c4*4+3)*129+jj] = v.w;
    }
    __syncthreads();
    mma_64x128(As, Bs, acc, ty, tx);
    __syncthreads();
  }
  float* out = g_s1 + ((size_t)b*T_ + t)*N_*N_;
#pragma unroll
  for (int ii=0;ii<4;ii++){
    int i = i0 + ty*4 + ii;
#pragma unroll
    for (int jj=0;jj<8;jj++)
      out[(size_t)i*N_ + j0 + tx*8 + jj] = acc[ii][jj];
  }
}

// ---------------- K4: softmax over t + diag mask + wsum (per (b,i)) ---------
__global__ __launch_bounds__(256)
void k_softmax(const float* __restrict__ R) {
  extern __shared__ float sm[];
  float* qrS = sm;            // 64*32
  float* qbS = qrS + 64*32;   // 64
  float* Rs  = qbS + 64;      // 256*33
  float* wp  = Rs + 256*33;   // 8*64
  int bi = blockIdx.x;
  int b = bi / N_, i = bi % N_;
  int j = threadIdx.x;
  int warp = j >> 5, lane = j & 31;

  for (int l = j; l < 64*32; l += 256) qrS[l] = g_qr[(size_t)bi*T_*DR_ + l];
  if (j < 64) qbS[j] = g_qb[(size_t)bi*T_ + j];
  for (int l = j; l < 256*8; l += 256) {
    int jr = l >> 3, c4 = l & 7;
    float4 v = *(const float4*)(R + ((size_t)bi*N_ + jr)*DR_ + c4*4);
    Rs[jr*33+c4*4+0] = v.x; Rs[jr*33+c4*4+1] = v.y;
    Rs[jr*33+c4*4+2] = v.z; Rs[jr*33+c4*4+3] = v.w;
  }
  __syncthreads();

  float rreg[32];
#pragma unroll
  for (int r=0;r<32;r++) rreg[r] = Rs[j*33+r];

  const float scale = 0.08838834764831845f;   // 1/sqrt(128)
  float sc[64];
  float m = -1e30f;
  const float* s1p = g_s1 + ((size_t)b*T_*N_ + i)*N_ + j;
#pragma unroll
  for (int t = 0; t < 64; t++) {
    float s2 = qbS[t];
#pragma unroll
    for (int r = 0; r < 32; r++) s2 = fmaf(qrS[t*32+r], rreg[r], s2);
    float s = (s1p[(size_t)t*N_*N_] + s2) * scale;
    sc[t] = s;
    m = fmaxf(m, s);
  }
  float den = 0.f;
#pragma unroll
  for (int t = 0; t < 64; t++) { float p = __expf(sc[t]-m); sc[t] = p; den += p; }
  float inv = (j == i) ? 0.f : 1.f/den;

  float* wout = g_w + (size_t)bi*T_*N_ + j;
#pragma unroll
  for (int t = 0; t < 64; t++) {
    float wv = sc[t]*inv;
    wout[(size_t)t*N_] = wv;
    float s = wv;
    s += __shfl_xor_sync(0xffffffffu, s, 16);
    s += __shfl_xor_sync(0xffffffffu, s, 8);
    s += __shfl_xor_sync(0xffffffffu, s, 4);
    s += __shfl_xor_sync(0xffffffffu, s, 2);
    s += __shfl_xor_sync(0xffffffffu, s, 1);
    if (lane == 0) wp[warp*64 + t] = s;
  }
  __syncthreads();
  if (j < 64) {
    float s = 0.f;
#pragma unroll
    for (int ww = 0; ww < 8; ww++) s += wp[ww*64 + j];
    g_ws[(size_t)bi*T_ + j] = s;
  }
}

// ---------------- K5: Hw[b,i,t,d] = sum_j w * H[b,j,t,d]  (per (b,t)) -------
__global__ __launch_bounds__(256)
void k_hw(const float* __restrict__ H) {
  extern __shared__ float sm[];
  float* As = sm;            // 64*33
  float* Bs = As + 64*33;    // 32*129
  int bt = blockIdx.y;
  int b = bt / T_, t = bt % T_;
  int i0 = blockIdx.x * 64;
  int tid = threadIdx.x, ty = tid >> 4, tx = tid & 15;
  float acc[4][8];
#pragma unroll
  for (int ii=0;ii<4;ii++)
#pragma unroll
    for (int jj=0;jj<8;jj++) acc[ii][jj]=0.f;

  for (int kc = 0; kc < 8; kc++) {
    int j0 = kc*32;
    for (int l = tid; l < 64*8; l += 256) {
      int r = l >> 3, c4 = l & 7;
      float4 v = *(const float4*)(g_w + (((size_t)b*N_ + i0+r)*T_ + t)*N_ + j0 + c4*4);
      As[r*33+c4*4+0] = v.x; As[r*33+c4*4+1] = v.y;
      As[r*33+c4*4+2] = v.z; As[r*33+c4*4+3] = v.w;
    }
    for (int l = tid; l < 32*32; l += 256) {
      int r = l >> 5, c4 = l & 31;
      float4 v = *(const float4*)(H + (((size_t)b*N_ + j0+r)*T_ + t)*D_ + c4*4);
      Bs[r*129+c4*4+0] = v.x; Bs[r*129+c4*4+1] = v.y;
      Bs[r*129+c4*4+2] = v.z; Bs[r*129+c4*4+3] = v.w;
    }
    __syncthreads();
    mma_64x128(As, Bs, acc, ty, tx);
    __syncthreads();
  }
#pragma unroll
  for (int ii=0;ii<4;ii++){
    int i = i0 + ty*4 + ii;
#pragma unroll
    for (int jj=0;jj<8;jj++)
      g_Hw[(((size_t)b*N_ + i)*T_ + t)*D_ + tx*8 + jj] = acc[ii][jj];
  }
}

// ---------------- K6: Dw = w @ dsum, Rw = w @ R  (per (b,i)) ----------------
__global__ __launch_bounds__(256)
void k_dwrw(const float* __restrict__ R) {
  extern __shared__ float sm[];
  float* As = sm;             // 64*33
  float* Bs = As + 64*33;     // 32*129
  float* Br = Bs + 32*129;    // 32*33
  int bi = blockIdx.x;
  int b = bi / N_;
  int tid = threadIdx.x, ty = tid >> 4, tx = tid & 15;
  float acc[4][8], acc2[4][2];
#pragma unroll
  for (int ii=0;ii<4;ii++){
#pragma unroll
    for (int jj=0;jj<8;jj++) acc[ii][jj]=0.f;
    acc2[ii][0]=0.f; acc2[ii][1]=0.f;
  }
  for (int kc = 0; kc < 8; kc++) {
    int j0 = kc*32;
    for (int l = tid; l < 64*8; l += 256) {
      int r = l >> 3, c4 = l & 7;
      float4 v = *(const float4*)(g_w + ((size_t)bi*T_ + r)*N_ + j0 + c4*4);
      As[r*33+c4*4+0] = v.x; As[r*33+c4*4+1] = v.y;
      As[r*33+c4*4+2] = v.z; As[r*33+c4*4+3] = v.w;
    }
    for (int l = tid; l < 32*32; l += 256) {
      int r = l >> 5, c4 = l & 31;
      float4 v = *(const float4*)(g_ds + ((size_t)b*N_ + j0+r)*D_ + c4*4);
      Bs[r*129+c4*4+0] = v.x; Bs[r*129+c4*4+1] = v.y;
      Bs[r*129+c4*4+2] = v.z; Bs[r*129+c4*4+3] = v.w;
    }
    for (int l = tid; l < 32*8; l += 256) {
      int r = l >> 3, c4 = l & 7;
      float4 v = *(const float4*)(R + ((size_t)bi*N_ + j0+r)*DR_ + c4*4);
      Br[r*33+c4*4+0] = v.x; Br[r*33+c4*4+1] = v.y;
      Br[r*33+c4*4+2] = v.z; Br[r*33+c4*4+3] = v.w;
    }
    __syncthreads();
#pragma unroll
    for (int kk = 0; kk < 32; kk++) {
      float a[4], bv[8], b2[2];
#pragma unroll
      for (int ii=0;ii<4;ii++) a[ii] = As[(ty*4+ii)*33+kk];
#pragma unroll
      for (int jj=0;jj<8;jj++) bv[jj] = Bs[kk*129+tx*8+jj];
      b2[0] = Br[kk*33+tx*2]; b2[1] = Br[kk*33+tx*2+1];
#pragma unroll
      for (int ii=0;ii<4;ii++){
#pragma unroll
        for (int jj=0;jj<8;jj++) acc[ii][jj] = fmaf(a[ii], bv[jj], acc[ii][jj]);
        acc2[ii][0] = fmaf(a[ii], b2[0], acc2[ii][0]);
        acc2[ii][1] = fmaf(a[ii], b2[1], acc2[ii][1]);
      }
    }
    __syncthreads();
  }
#pragma unroll
  for (int ii=0;ii<4;ii++){
    int t = ty*4+ii;
#pragma unroll
    for (int jj=0;jj<8;jj++)
      g_Dw[((size_t)bi*T_ + t)*D_ + tx*8 + jj] = acc[ii][jj];
    g_Rw[((size_t)bi*T_ + t)*DR_ + tx*2    ] = acc2[ii][0];
    g_Rw[((size_t)bi*T_ + t)*DR_ + tx*2 + 1] = acc2[ii][1];
  }
}

// ---------------- K7: z = [H*ws|Hw|Rw|Dw] @ Wf^T + bf*ws; x=H+z; LayerNorm --
__global__ __launch_bounds__(256)
void k_final(const float* __restrict__ H, const float* __restrict__ Wf,
             const float* __restrict__ bf, const float* __restrict__ gamma,
             const float* __restrict__ beta, float* __restrict__ out) {
  extern __shared__ float sm[];
  float* As  = sm;             // 64*33
  float* Bs  = As + 64*33;     // 32*129
  float* wsS = Bs + 32*129;    // 64
  float* rs  = wsS + 64;       // 64
  float* rs2 = rs + 64;        // 64
  int bi = blockIdx.x;
  int tid = threadIdx.x, ty = tid >> 4, tx = tid & 15;
  if (tid < 64) wsS[tid] = g_ws[(size_t)bi*T_ + tid];
  __syncthreads();

  const float* Hrow = H + (size_t)bi*T_*D_;
  float acc[4][8];
#pragma unroll
  for (int ii=0;ii<4;ii++)
#pragma unroll
    for (int jj=0;jj<8;jj++) acc[ii][jj]=0.f;

  for (int kc = 0; kc < 13; kc++) {
    int c0 = kc*32;
    for (int l = tid; l < 64*8; l += 256) {
      int r = l >> 3, c4 = l & 7;
      int cc = c0 + c4*4;
      float4 v;
      if (cc < 128) {
        v = *(const float4*)(Hrow + r*D_ + cc);
        float wsv = wsS[r];
        v.x *= wsv; v.y *= wsv; v.z *= wsv; v.w *= wsv;
      } else if (cc < 256) {
        v = *(const float4*)(g_Hw + (size_t)bi*T_*D_  + r*D_  + cc-128);
      } else if (cc < 288) {
        v = *(const float4*)(g_Rw + (size_t)bi*T_*DR_ + r*DR_ + cc-256);
      } else {
        v = *(const float4*)(g_Dw + (size_t)bi*T_*D_  + r*D_  + cc-288);
      }
      As[r*33+c4*4+0] = v.x; As[r*33+c4*4+1] = v.y;
      As[r*33+c4*4+2] = v.z; As[r*33+c4*4+3] = v.w;
    }
    for (int l = tid; l < 128*8; l += 256) {
      int e = l >> 3, c4 = l & 7;
      float4 v = *(const float4*)(Wf + (size_t)e*WLD + c0 + c4*4);
      Bs[(c4*4+0)*129+e] = v.x; Bs[(c4*4+1)*129+e] = v.y;
      Bs[(c4*4+2)*129+e] = v.z; Bs[(c4*4+3)*129+e] = v.w;
    }
    __syncthreads();
    mma_64x128(As, Bs, acc, ty, tx);
    __syncthreads();
  }

  float x[4][8];
#pragma unroll
  for (int ii=0;ii<4;ii++){
    int t = ty*4+ii;
    float wsv = wsS[t];
#pragma unroll
    for (int jj=0;jj<8;jj++){
      int e = tx*8+jj;
      x[ii][jj] = Hrow[t*D_+e] + acc[ii][jj] + bf[e]*wsv;
    }
  }
  // LayerNorm: reduce each row across the 16 tx lanes
#pragma unroll
  for (int ii=0;ii<4;ii++){
    float s = 0.f, s2 = 0.f;
#pragma unroll
    for (int jj=0;jj<8;jj++){ s += x[ii][jj]; s2 += x[ii][jj]*x[ii][jj]; }
#pragma unroll
    for (int o = 8; o >= 1; o >>= 1) {
      s  += __shfl_xor_sync(0xffffffffu, s,  o);
      s2 += __shfl_xor_sync(0xffffffffu, s2, o);
    }
    if (tx == 0) { rs[ty*4+ii] = s; rs2[ty*4+ii] = s2; }
  }
  __syncthreads();
#pragma unroll
  for (int ii=0;ii<4;ii++){
    int t = ty*4+ii;
    float mu   = rs[t]  * (1.f/D_);
    float var  = rs2[t] * (1.f/D_) - mu*mu;
    float rstd = rsqrtf(var + 1e-5f);
#pragma unroll
    for (int jj=0;jj<8;jj++){
      int e = tx*8+jj;
      out[(size_t)bi*T_*D_ + t*D_ + e] = (x[ii][jj]-mu)*rstd*gamma[e] + beta[e];
    }
  }
}

// ---------------- launch ----------------------------------------------------
extern "C" void kernel_launch(void* const* d_in, const int* in_sizes, int n_in,
                              void* d_out, int out_size) {
  const float* H     = (const float*)d_in[0];
  const float* R     = (const float*)d_in[1];
  const float* dH    = (const float*)d_in[2];
  const float* Wq    = (const float*)d_in[3];
  const float* bq    = (const float*)d_in[4];
  const float* Wk    = (const float*)d_in[5];
  const float* bk    = (const float*)d_in[6];
  const float* Wr    = (const float*)d_in[7];
  const float* br    = (const float*)d_in[8];
  const float* Wf    = (const float*)d_in[9];
  const float* bf    = (const float*)d_in[10];
  const float* gamma = (const float*)d_in[11];
  const float* beta  = (const float*)d_in[12];
  float* out = (float*)d_out;

  const int smProj = (64*33 + 2*32*129) * 4;          // 41472
  const int smQr   = (64*130) * 4;                    // 33280
  const int smS1   = (64*33 + 32*129) * 4;            // 24960
  const int smSm   = (64*32 + 64 + 256*33 + 512) * 4; // 44288
  const int smHw   = smS1;
  const int smDw   = (64*33 + 32*129 + 32*33) * 4;    // 29184
  const int smFn   = (64*33 + 32*129 + 3*64) * 4;     // 25728

  k_proj   <<<B_*N_, 256, smProj>>>(H, Wq, bq, Wk, bk);
  k_qr     <<<B_*N_, 256, smQr  >>>(Wr, br);
  k_dsum   <<<B_*N_, 128        >>>(dH);
  k_s1     <<<dim3(8, B_*T_), 256, smS1>>>();
  k_softmax<<<B_*N_, 256, smSm  >>>(R);
  k_hw     <<<dim3(4, B_*T_), 256, smHw>>>(H);
  k_dwrw   <<<B_*N_, 256, smDw  >>>(R);
  k_final  <<<B_*N_, 256, smFn  >>>(H, Wf, bf, gamma, beta, out);
}

// round 4
// speedup vs baseline: 2.3515x; 2.3515x over previous
#include <cuda_runtime.h>
#include <cstdint>

#define B_  4
#define N_  256
#define T_  64
#define D_  128
#define DH_ 128
#define DR_ 32
#define WLD (3*D_+DR_)   // 416

// ---------------- scratch (device globals; no allocations allowed) ----------
__device__ float g_q [B_*N_*T_*DH_];   // (b,i,t,h)
__device__ float g_k [B_*N_*T_*DH_];   // (b,j,t,h)
__device__ float g_qr[B_*N_*T_*DR_];   // (b,i,t,r)  = q @ Wr
__device__ float g_qb[B_*N_*T_];       // (b,i,t)    = q @ br
__device__ float g_s1[B_*T_*N_*N_];    // (b,t,i,j)  = q.k
__device__ float g_w [B_*N_*T_*N_];    // (b,i,t,j)  softmax weights (diag-masked)
__device__ float g_ws[B_*N_*T_];       // (b,i,t)    = sum_j w
__device__ float g_ds[B_*N_*D_];       // (b,j,d)    = sum_t delta_H
__device__ float g_Hw[B_*N_*T_*D_];    // (b,i,t,d)  = sum_j w * H[b,j,t,:]
__device__ float g_Dw[B_*N_*T_*D_];    // (b,i,t,d)  = sum_j w * dsum[b,j,:]
__device__ float g_Rw[B_*N_*T_*DR_];   // (b,i,t,r)  = sum_j w * R[b,i,j,:]

// ---------------- tf32 helpers ----------------------------------------------
__device__ __forceinline__ float t32(float x) {
  uint32_t u;
  asm("cvt.rna.tf32.f32 %0, %1;" : "=r"(u) : "f"(x));
  return __uint_as_float(u);
}
__device__ __forceinline__ float4 t32v(float4 v) {
  v.x = t32(v.x); v.y = t32(v.y); v.z = t32(v.z); v.w = t32(v.w);
  return v;
}
__device__ __forceinline__ void mma_tf32(float c[4],
    uint32_t a0, uint32_t a1, uint32_t a2, uint32_t a3,
    uint32_t b0, uint32_t b1) {
  asm volatile(
    "mma.sync.aligned.m16n8k8.row.col.f32.tf32.tf32.f32 "
    "{%0,%1,%2,%3},{%4,%5,%6,%7},{%8,%9},{%0,%1,%2,%3};"
    : "+f"(c[0]), "+f"(c[1]), "+f"(c[2]), "+f"(c[3])
    : "r"(a0), "r"(a1), "r"(a2), "r"(a3), "r"(b0), "r"(b1));
}

// Per-warp 16x(8*NF) tile, one 32-wide K chunk. As: [64][36] m-major.
// Bs: [n][36] n-major (mma .col operand). Conflict-free on both.
template<int NF>
__device__ __forceinline__ void warp_mma_chunk(const float* __restrict__ As,
                                               const float* __restrict__ Bs,
                                               float (&c)[NF][4],
                                               int mbase, int nbase,
                                               int tr, int tc) {
#pragma unroll
  for (int k = 0; k < 32; k += 8) {
    uint32_t a0 = __float_as_uint(As[(mbase+tr  )*36 + k+tc  ]);
    uint32_t a1 = __float_as_uint(As[(mbase+tr+8)*36 + k+tc  ]);
    uint32_t a2 = __float_as_uint(As[(mbase+tr  )*36 + k+tc+4]);
    uint32_t a3 = __float_as_uint(As[(mbase+tr+8)*36 + k+tc+4]);
#pragma unroll
    for (int nf = 0; nf < NF; nf++) {
      uint32_t b0 = __float_as_uint(Bs[(nbase+nf*8+tr)*36 + k+tc  ]);
      uint32_t b1 = __float_as_uint(Bs[(nbase+nf*8+tr)*36 + k+tc+4]);
      mma_tf32(c[nf], a0, a1, a2, a3, b0, b1);
    }
  }
}

// ---------------- K1: q = H Wq^T + bq, k = H Wk^T + bk (per (b,i)) ----------
__global__ __launch_bounds__(256)
void k_proj(const float* __restrict__ H,
            const float* __restrict__ Wq, const float* __restrict__ bq,
            const float* __restrict__ Wk, const float* __restrict__ bk) {
  extern __shared__ float sm[];
  float* As = sm;            // 64*36
  float* Bs = As + 64*36;    // 256*36
  int bi = blockIdx.x;
  int tid = threadIdx.x, wid = tid >> 5, lane = tid & 31;
  int tr = lane >> 2, tc = lane & 3;
  int mbase = (wid >> 1) * 16, nbase = (wid & 1) * 128;
  const float* Hrow = H + (size_t)bi*T_*D_;

  float c[16][4];
#pragma unroll
  for (int nf=0;nf<16;nf++) { c[nf][0]=c[nf][1]=c[nf][2]=c[nf][3]=0.f; }

  for (int kc = 0; kc < 4; kc++) {
    int c0 = kc*32;
    for (int l = tid; l < 64*8; l += 256) {
      int r = l >> 3, c4 = l & 7;
      *(float4*)(As + r*36 + c4*4) = t32v(*(const float4*)(Hrow + r*D_ + c0 + c4*4));
    }
    for (int l = tid; l < 256*8; l += 256) {
      int n = l >> 3, c4 = l & 7;
      const float* src = (n < 128) ? (Wq + (size_t)n*D_) : (Wk + (size_t)(n-128)*D_);
      *(float4*)(Bs + n*36 + c4*4) = t32v(*(const float4*)(src + c0 + c4*4));
    }
    __syncthreads();
    warp_mma_chunk<16>(As, Bs, c, mbase, nbase, tr, tc);
    __syncthreads();
  }
  float* qout = g_q + (size_t)bi*T_*DH_;
  float* kout = g_k + (size_t)bi*T_*DH_;
#pragma unroll
  for (int nf = 0; nf < 16; nf++) {
    int col = nbase + nf*8 + tc*2;
    int r0 = mbase + tr, r1 = r0 + 8;
    if (col < 128) {
      qout[r0*DH_+col  ] = c[nf][0] + bq[col];
      qout[r0*DH_+col+1] = c[nf][1] + bq[col+1];
      qout[r1*DH_+col  ] = c[nf][2] + bq[col];
      qout[r1*DH_+col+1] = c[nf][3] + bq[col+1];
    } else {
      int h = col - 128;
      kout[r0*DH_+h  ] = c[nf][0] + bk[h];
      kout[r0*DH_+h+1] = c[nf][1] + bk[h+1];
      kout[r1*DH_+h  ] = c[nf][2] + bk[h];
      kout[r1*DH_+h+1] = c[nf][3] + bk[h+1];
    }
  }
}

// ---------------- K1b: qr = q Wr, qb = q . br (per (b,i)) -------------------
__global__ __launch_bounds__(256)
void k_qr(const float* __restrict__ Wr, const float* __restrict__ br) {
  extern __shared__ float sm[];   // Qs[64][130]
  float* Qs = sm;
  int bi = blockIdx.x, tid = threadIdx.x;
  const float* qsrc = g_q + (size_t)bi*T_*DH_;
  for (int l = tid; l < T_*DH_/4; l += 256) {
    int t = l >> 5, c4 = l & 31;
    float4 v = *(const float4*)(qsrc + t*DH_ + c4*4);
    Qs[t*130+c4*4+0] = v.x; Qs[t*130+c4*4+1] = v.y;
    Qs[t*130+c4*4+2] = v.z; Qs[t*130+c4*4+3] = v.w;
  }
  __syncthreads();
  int t = tid >> 2, rg = tid & 3;
  float acc[8];
#pragma unroll
  for (int rr=0;rr<8;rr++) acc[rr]=0.f;
  for (int h = 0; h < DH_; h++) {
    float qv = Qs[t*130+h];
#pragma unroll
    for (int rr=0;rr<8;rr++) acc[rr] = fmaf(qv, Wr[h*DR_ + rg*8 + rr], acc[rr]);
  }
  float* qrout = g_qr + (size_t)bi*T_*DR_ + t*DR_ + rg*8;
#pragma unroll
  for (int rr=0;rr<8;rr++) qrout[rr] = acc[rr];

  if (tid < T_) {
    float s = 0.f;
    for (int h = 0; h < DH_; h++) s = fmaf(Qs[tid*130+h], br[h], s);
    g_qb[(size_t)bi*T_ + tid] = s;
  }
}

// ---------------- K2: dsum = sum_t delta_H ----------------------------------
__global__ __launch_bounds__(128)
void k_dsum(const float* __restrict__ dH) {
  int bj = blockIdx.x, d = threadIdx.x;
  const float* p = dH + (size_t)bj*T_*D_ + d;
  float s = 0.f;
#pragma unroll 8
  for (int t = 0; t < T_; t++) s += p[t*D_];
  g_ds[(size_t)bj*D_ + d] = s;
}

// ---------------- K3: s1[b,t,i,j] = q.k   (per (b,t), tiled) ----------------
__global__ __launch_bounds__(256)
void k_s1() {
  extern __shared__ float sm[];
  float* As = sm;            // 64*36
  float* Bs = As + 64*36;    // 128*36
  int bt = blockIdx.y;
  int b = bt / T_, t = bt % T_;
  int i0 = (blockIdx.x & 3) * 64;
  int j0 = (blockIdx.x >> 2) * 128;
  int tid = threadIdx.x, wid = tid >> 5, lane = tid & 31;
  int tr = lane >> 2, tc = lane & 3;
  int mbase = (wid >> 1) * 16, nbase = (wid & 1) * 64;

  float c[8][4];
#pragma unroll
  for (int nf=0;nf<8;nf++) { c[nf][0]=c[nf][1]=c[nf][2]=c[nf][3]=0.f; }

  for (int kc = 0; kc < 4; kc++) {
    int h0 = kc*32;
    for (int l = tid; l < 64*8; l += 256) {
      int r = l >> 3, c4 = l & 7;
      *(float4*)(As + r*36 + c4*4) =
        t32v(*(const float4*)(g_q + (((size_t)b*N_ + i0+r)*T_ + t)*DH_ + h0 + c4*4));
    }
    for (int l = tid; l < 128*8; l += 256) {
      int n = l >> 3, c4 = l & 7;
      *(float4*)(Bs + n*36 + c4*4) =
        t32v(*(const float4*)(g_k + (((size_t)b*N_ + j0+n)*T_ + t)*DH_ + h0 + c4*4));
    }
    __syncthreads();
    warp_mma_chunk<8>(As, Bs, c, mbase, nbase, tr, tc);
    __syncthreads();
  }
  float* out = g_s1 + ((size_t)b*T_ + t)*N_*N_;
#pragma unroll
  for (int nf = 0; nf < 8; nf++) {
    int col = j0 + nbase + nf*8 + tc*2;
    int r0 = i0 + mbase + tr, r1 = r0 + 8;
    out[(size_t)r0*N_+col  ] = c[nf][0];
    out[(size_t)r0*N_+col+1] = c[nf][1];
    out[(size_t)r1*N_+col  ] = c[nf][2];
    out[(size_t)r1*N_+col+1] = c[nf][3];
  }
}

// ---------------- K4: softmax over t + diag mask + wsum (per (b,i)) ---------
__global__ __launch_bounds__(256)
void k_softmax(const float* __restrict__ R) {
  extern __shared__ float sm[];
  float* qrS = sm;            // 64*32
  float* qbS = qrS + 64*32;   // 64
  float* Rs  = qbS + 64;      // 256*33
  float* wp  = Rs + 256*33;   // 8*64
  int bi = blockIdx.x;
  int b = bi / N_, i = bi % N_;
  int j = threadIdx.x;
  int warp = j >> 5, lane = j & 31;

  for (int l = j; l < 64*32; l += 256) qrS[l] = g_qr[(size_t)bi*T_*DR_ + l];
  if (j < 64) qbS[j] = g_qb[(size_t)bi*T_ + j];
  for (int l = j; l < 256*8; l += 256) {
    int jr = l >> 3, c4 = l & 7;
    float4 v = *(const float4*)(R + ((size_t)bi*N_ + jr)*DR_ + c4*4);
    Rs[jr*33+c4*4+0] = v.x; Rs[jr*33+c4*4+1] = v.y;
    Rs[jr*33+c4*4+2] = v.z; Rs[jr*33+c4*4+3] = v.w;
  }
  __syncthreads();

  float rreg[32];
#pragma unroll
  for (int r=0;r<32;r++) rreg[r] = Rs[j*33+r];

  const float scale = 0.08838834764831845f;   // 1/sqrt(128)
  float sc[64];
  float m = -1e30f;
  const float* s1p = g_s1 + ((size_t)b*T_*N_ + i)*N_ + j;
#pragma unroll
  for (int t = 0; t < 64; t++) {
    float s2 = qbS[t];
#pragma unroll
    for (int r = 0; r < 32; r++) s2 = fmaf(qrS[t*32+r], rreg[r], s2);
    float s = (s1p[(size_t)t*N_*N_] + s2) * scale;
    sc[t] = s;
    m = fmaxf(m, s);
  }
  float den = 0.f;
#pragma unroll
  for (int t = 0; t < 64; t++) { float p = __expf(sc[t]-m); sc[t] = p; den += p; }
  float inv = (j == i) ? 0.f : 1.f/den;

  float* wout = g_w + (size_t)bi*T_*N_ + j;
#pragma unroll
  for (int t = 0; t < 64; t++) {
    float wv = sc[t]*inv;
    wout[(size_t)t*N_] = wv;
    float s = wv;
    s += __shfl_xor_sync(0xffffffffu, s, 16);
    s += __shfl_xor_sync(0xffffffffu, s, 8);
    s += __shfl_xor_sync(0xffffffffu, s, 4);
    s += __shfl_xor_sync(0xffffffffu, s, 2);
    s += __shfl_xor_sync(0xffffffffu, s, 1);
    if (lane == 0) wp[warp*64 + t] = s;
  }
  __syncthreads();
  if (j < 64) {
    float s = 0.f;
#pragma unroll
    for (int ww = 0; ww < 8; ww++) s += wp[ww*64 + j];
    g_ws[(size_t)bi*T_ + j] = s;
  }
}

// ---------------- K5: Hw[b,i,t,d] = sum_j w * H[b,j,t,d]  (per (b,t)) -------
__global__ __launch_bounds__(256)
void k_hw(const float* __restrict__ H) {
  extern __shared__ float sm[];
  float* As = sm;            // 64*36
  float* Bs = As + 64*36;    // 128*36
  int bt = blockIdx.y;
  int b = bt / T_, t = bt % T_;
  int i0 = blockIdx.x * 64;
  int tid = threadIdx.x, wid = tid >> 5, lane = tid & 31;
  int tr = lane >> 2, tc = lane & 3;
  int mbase = (wid >> 1) * 16, nbase = (wid & 1) * 64;

  float c[8][4];
#pragma unroll
  for (int nf=0;nf<8;nf++) { c[nf][0]=c[nf][1]=c[nf][2]=c[nf][3]=0.f; }

  for (int kc = 0; kc < 8; kc++) {
    int j0 = kc*32;
    for (int l = tid; l < 64*8; l += 256) {
      int r = l >> 3, c4 = l & 7;
      *(float4*)(As + r*36 + c4*4) =
        t32v(*(const float4*)(g_w + (((size_t)b*N_ + i0+r)*T_ + t)*N_ + j0 + c4*4));
    }
    // transpose fill: Bs[n=d][k=j] from H[j][d]; lanes take consecutive j
    for (int l = tid; l < 32*32; l += 256) {
      int jj = l & 31, c4 = l >> 5;
      float4 v = t32v(*(const float4*)(H + (((size_t)b*N_ + j0+jj)*T_ + t)*D_ + c4*4));
      Bs[(c4*4+0)*36 + jj] = v.x; Bs[(c4*4+1)*36 + jj] = v.y;
      Bs[(c4*4+2)*36 + jj] = v.z; Bs[(c4*4+3)*36 + jj] = v.w;
    }
    __syncthreads();
    warp_mma_chunk<8>(As, Bs, c, mbase, nbase, tr, tc);
    __syncthreads();
  }
#pragma unroll
  for (int nf = 0; nf < 8; nf++) {
    int col = nbase + nf*8 + tc*2;
    int r0 = mbase + tr, r1 = r0 + 8;
    g_Hw[(((size_t)b*N_ + i0+r0)*T_ + t)*D_ + col  ] = c[nf][0];
    g_Hw[(((size_t)b*N_ + i0+r0)*T_ + t)*D_ + col+1] = c[nf][1];
    g_Hw[(((size_t)b*N_ + i0+r1)*T_ + t)*D_ + col  ] = c[nf][2];
    g_Hw[(((size_t)b*N_ + i0+r1)*T_ + t)*D_ + col+1] = c[nf][3];
  }
}

// ---------------- K6: Dw = w @ dsum, Rw = w @ R  (per (b,i)) ----------------
__global__ __launch_bounds__(256)
void k_dwrw(const float* __restrict__ R) {
  extern __shared__ float sm[];
  float* As = sm;             // 64*36
  float* Bs = As + 64*36;     // 160*36
  int bi = blockIdx.x;
  int b = bi / N_;
  int tid = threadIdx.x, wid = tid >> 5, lane = tid & 31;
  int tr = lane >> 2, tc = lane & 3;
  int mbase = (wid >> 1) * 16, nbase = (wid & 1) * 80;

  float c[10][4];
#pragma unroll
  for (int nf=0;nf<10;nf++) { c[nf][0]=c[nf][1]=c[nf][2]=c[nf][3]=0.f; }

  for (int kc = 0; kc < 8; kc++) {
    int j0 = kc*32;
    for (int l = tid; l < 64*8; l += 256) {
      int r = l >> 3, c4 = l & 7;
      *(float4*)(As + r*36 + c4*4) =
        t32v(*(const float4*)(g_w + ((size_t)bi*T_ + r)*N_ + j0 + c4*4));
    }
    // Bs[n<128] from g_ds[j][d] (transpose, lane-consecutive j)
    for (int l = tid; l < 32*32; l += 256) {
      int jj = l & 31, c4 = l >> 5;
      float4 v = t32v(*(const float4*)(g_ds + ((size_t)b*N_ + j0+jj)*D_ + c4*4));
      Bs[(c4*4+0)*36 + jj] = v.x; Bs[(c4*4+1)*36 + jj] = v.y;
      Bs[(c4*4+2)*36 + jj] = v.z; Bs[(c4*4+3)*36 + jj] = v.w;
    }
    // Bs[128..159] from R[j][r] (transpose)
    for (int l = tid; l < 32*8; l += 256) {
      int jj = l & 31, c4 = l >> 5;
      float4 v = t32v(*(const float4*)(R + ((size_t)bi*N_ + j0+jj)*DR_ + c4*4));
      Bs[(128+c4*4+0)*36 + jj] = v.x; Bs[(128+c4*4+1)*36 + jj] = v.y;
      Bs[(128+c4*4+2)*36 + jj] = v.z; Bs[(128+c4*4+3)*36 + jj] = v.w;
    }
    __syncthreads();
    warp_mma_chunk<10>(As, Bs, c, mbase, nbase, tr, tc);
    __syncthreads();
  }
#pragma unroll
  for (int nf = 0; nf < 10; nf++) {
    int col = nbase + nf*8 + tc*2;
    int r0 = mbase + tr, r1 = r0 + 8;
    if (col < 128) {
      g_Dw[((size_t)bi*T_ + r0)*D_ + col  ] = c[nf][0];
      g_Dw[((size_t)bi*T_ + r0)*D_ + col+1] = c[nf][1];
      g_Dw[((size_t)bi*T_ + r1)*D_ + col  ] = c[nf][2];
      g_Dw[((size_t)bi*T_ + r1)*D_ + col+1] = c[nf][3];
    } else {
      int cr = col - 128;
      g_Rw[((size_t)bi*T_ + r0)*DR_ + cr  ] = c[nf][0];
      g_Rw[((size_t)bi*T_ + r0)*DR_ + cr+1] = c[nf][1];
      g_Rw[((size_t)bi*T_ + r1)*DR_ + cr  ] = c[nf][2];
      g_Rw[((size_t)bi*T_ + r1)*DR_ + cr+1] = c[nf][3];
    }
  }
}

// ---------------- K7: z = [H*ws|Hw|Rw|Dw] @ Wf^T + bf*ws; x=H+z; LayerNorm --
__global__ __launch_bounds__(256)
void k_final(const float* __restrict__ H, const float* __restrict__ Wf,
             const float* __restrict__ bf, const float* __restrict__ gamma,
             const float* __restrict__ beta, float* __restrict__ out) {
  extern __shared__ float sm[];
  float* As  = sm;             // 64*36   (overlaid by Xs later)
  float* Bs  = As + 64*36;     // 128*36
  float* Xs  = sm;             // 64*132 overlay (after GEMM)
  float* wsS = sm + 64*132;    // 64
  int bi = blockIdx.x;
  int tid = threadIdx.x, wid = tid >> 5, lane = tid & 31;
  int tr = lane >> 2, tc = lane & 3;
  int mbase = (wid >> 1) * 16, nbase = (wid & 1) * 64;
  if (tid < 64) wsS[tid] = g_ws[(size_t)bi*T_ + tid];
  __syncthreads();

  const float* Hrow = H + (size_t)bi*T_*D_;
  float c[8][4];
#pragma unroll
  for (int nf=0;nf<8;nf++) { c[nf][0]=c[nf][1]=c[nf][2]=c[nf][3]=0.f; }

  for (int kc = 0; kc < 13; kc++) {
    int c0 = kc*32;
    for (int l = tid; l < 64*8; l += 256) {
      int r = l >> 3, c4 = l & 7;
      int cc = c0 + c4*4;
      float4 v;
      if (cc < 128) {
        v = *(const float4*)(Hrow + r*D_ + cc);
        float wsv = wsS[r];
        v.x *= wsv; v.y *= wsv; v.z *= wsv; v.w *= wsv;
      } else if (cc < 256) {
        v = *(const float4*)(g_Hw + (size_t)bi*T_*D_  + r*D_  + cc-128);
      } else if (cc < 288) {
        v = *(const float4*)(g_Rw + (size_t)bi*T_*DR_ + r*DR_ + cc-256);
      } else {
        v = *(const float4*)(g_Dw + (size_t)bi*T_*D_  + r*D_  + cc-288);
      }
      *(float4*)(As + r*36 + c4*4) = t32v(v);
    }
    for (int l = tid; l < 128*8; l += 256) {
      int e = l >> 3, c4 = l & 7;
      *(float4*)(Bs + e*36 + c4*4) =
        t32v(*(const float4*)(Wf + (size_t)e*WLD + c0 + c4*4));
    }
    __syncthreads();
    warp_mma_chunk<8>(As, Bs, c, mbase, nbase, tr, tc);
    __syncthreads();
  }

  // x = H + z  -> Xs (overlays As/Bs; all accs live in regs now)
#pragma unroll
  for (int nf = 0; nf < 8; nf++) {
    int col = nbase + nf*8 + tc*2;
    int r0 = mbase + tr, r1 = r0 + 8;
    float ws0 = wsS[r0], ws1 = wsS[r1];
    Xs[r0*132+col  ] = Hrow[r0*D_+col  ] + c[nf][0] + bf[col  ]*ws0;
    Xs[r0*132+col+1] = Hrow[r0*D_+col+1] + c[nf][1] + bf[col+1]*ws0;
    Xs[r1*132+col  ] = Hrow[r1*D_+col  ] + c[nf][2] + bf[col  ]*ws1;
    Xs[r1*132+col+1] = Hrow[r1*D_+col+1] + c[nf][3] + bf[col+1]*ws1;
  }
  __syncthreads();

  // LayerNorm: each warp handles 8 rows; lane covers 4 cols
  float4 gm = *(const float4*)(gamma + lane*4);
  float4 bt4 = *(const float4*)(beta + lane*4);
#pragma unroll
  for (int rr = 0; rr < 8; rr++) {
    int row = wid*8 + rr;
    float4 v = *(const float4*)(Xs + row*132 + lane*4);
    float s  = v.x + v.y + v.z + v.w;
    float s2 = v.x*v.x + v.y*v.y + v.z*v.z + v.w*v.w;
#pragma unroll
    for (int o = 16; o >= 1; o >>= 1) {
      s  += __shfl_xor_sync(0xffffffffu, s,  o);
      s2 += __shfl_xor_sync(0xffffffffu, s2, o);
    }
    float mu   = s  * (1.f/D_);
    float var  = s2 * (1.f/D_) - mu*mu;
    float rstd = rsqrtf(var + 1e-5f);
    float* op = out + (size_t)bi*T_*D_ + row*D_ + lane*4;
    op[0] = (v.x-mu)*rstd*gm.x + bt4.x;
    op[1] = (v.y-mu)*rstd*gm.y + bt4.y;
    op[2] = (v.z-mu)*rstd*gm.z + bt4.z;
    op[3] = (v.w-mu)*rstd*gm.w + bt4.w;
  }
}

// ---------------- launch ----------------------------------------------------
extern "C" void kernel_launch(void* const* d_in, const int* in_sizes, int n_in,
                              void* d_out, int out_size) {
  const float* H     = (const float*)d_in[0];
  const float* R     = (const float*)d_in[1];
  const float* dH    = (const float*)d_in[2];
  const float* Wq    = (const float*)d_in[3];
  const float* bq    = (const float*)d_in[4];
  const float* Wk    = (const float*)d_in[5];
  const float* bk    = (const float*)d_in[6];
  const float* Wr    = (const float*)d_in[7];
  const float* br    = (const float*)d_in[8];
  const float* Wf    = (const float*)d_in[9];
  const float* bf    = (const float*)d_in[10];
  const float* gamma = (const float*)d_in[11];
  const float* beta  = (const float*)d_in[12];
  float* out = (float*)d_out;

  const int smProj = (64*36 + 256*36) * 4;            // 46080
  const int smQr   = (64*130) * 4;                    // 33280
  const int smS1   = (64*36 + 128*36) * 4;            // 27648
  const int smSm   = (64*32 + 64 + 256*33 + 512) * 4; // 44288
  const int smHw   = smS1;
  const int smDw   = (64*36 + 160*36) * 4;            // 32256
  const int smFn   = (64*132 + 64) * 4;               // 34048

  k_proj   <<<B_*N_, 256, smProj>>>(H, Wq, bq, Wk, bk);
  k_qr     <<<B_*N_, 256, smQr  >>>(Wr, br);
  k_dsum   <<<B_*N_, 128        >>>(dH);
  k_s1     <<<dim3(8, B_*T_), 256, smS1>>>();
  k_softmax<<<B_*N_, 256, smSm  >>>(R);
  k_hw     <<<dim3(4, B_*T_), 256, smHw>>>(H);
  k_dwrw   <<<B_*N_, 256, smDw  >>>(R);
  k_final  <<<B_*N_, 256, smFn  >>>(H, Wf, bf, gamma, beta, out);
}